// round 3
// baseline (speedup 1.0000x reference)
#include <cuda_runtime.h>
#include <cuda_bf16.h>

// Problem constants
// B=8, CIN=256, COUT=512, DK=256, DV=256, NH=8, H=W=32, DKH=DVH=32
#define HW 1024

// Scratch (static device globals: allocation-free rule)
__device__ float g_wT[2304 * 1024];      // combined conv weights, K-major: [(ci*9+k)][co] co: 0..255 conv, 256..1023 qkv
__device__ float g_watT[256 * 256];      // w_att transposed: [ci][co]
__device__ float g_qkv[8 * 768 * 1024];  // qkv conv output (b, 768, HW)
__device__ float g_att[8 * 256 * 1024];  // attention output, already in (b, C, H, W) layout for 1x1 conv

// ---------------------------------------------------------------------------
// Kernel 0: weight preparation (transpose to K-major)
// ---------------------------------------------------------------------------
__global__ void prep_weights(const float* __restrict__ wc,
                             const float* __restrict__ wq,
                             const float* __restrict__ wa) {
    int idx = blockIdx.x * 256 + threadIdx.x;
    if (idx < 2304 * 1024) {
        int co = idx & 1023;
        int rk = idx >> 10;          // ci*9 + k
        int ci = rk / 9;
        int k  = rk - ci * 9;
        float v = (co < 256) ? wc[(co * 256 + ci) * 9 + k]
                             : wq[((co - 256) * 256 + ci) * 9 + k];
        g_wT[idx] = v;
    }
    if (idx < 256 * 256) {
        int co = idx & 255;
        int ci = idx >> 8;
        g_watT[idx] = wa[co * 256 + ci];
    }
}

// ---------------------------------------------------------------------------
// Kernel 1: fused 3x3 conv (1024 output channels = 256 xo + 768 qkv)
// Block: 256 threads, tile = 64 co x 64 pixels (8x8 spatial), 4x4 per thread.
// ---------------------------------------------------------------------------
__global__ __launch_bounds__(256) void conv3x3_kernel(
    const float* __restrict__ x,
    const float* __restrict__ bconv,
    const float* __restrict__ bqkv,
    float* __restrict__ out) {
    __shared__ float Ws[72 * 64];      // [cil*9+k][64 co]
    __shared__ float Xs[8 * 10 * 12];  // [cil][10 rows][12 pitch]

    const int t  = threadIdx.x;
    const int tx = t & 15;       // co group
    const int ty = t >> 4;       // pixel group
    const int b      = blockIdx.z;
    const int coBase = blockIdx.x * 64;
    const int pt     = blockIdx.y;
    const int py0 = (pt >> 2) * 8;
    const int px0 = (pt & 3) * 8;
    const int r   = ty >> 1;           // row within 8x8 tile
    const int ccB = (ty & 1) * 4;      // col base within 8x8 tile

    float acc[4][4];
#pragma unroll
    for (int i = 0; i < 4; ++i)
#pragma unroll
        for (int j = 0; j < 4; ++j) acc[i][j] = 0.f;

    for (int ciBase = 0; ciBase < 256; ciBase += 8) {
        __syncthreads();
        // Load input patch with halo (8 ci x 10 x 10), zero-padded
#pragma unroll
        for (int i = 0; i < 4; ++i) {
            int idx = t + i * 256;
            if (idx < 800) {
                int cil = idx / 100;
                int rem = idx - cil * 100;
                int ly = rem / 10;
                int lx = rem - ly * 10;
                int gy = py0 + ly - 1;
                int gx = px0 + lx - 1;
                float v = 0.f;
                if ((unsigned)gy < 32u && (unsigned)gx < 32u)
                    v = x[((b * 256 + ciBase + cil) * 32 + gy) * 32 + gx];
                Xs[cil * 120 + ly * 12 + lx] = v;
            }
        }
        // Load weights (coalesced from K-major transposed buffer)
        {
            const float* src = &g_wT[(ciBase * 9) * 1024 + coBase];
#pragma unroll
            for (int i = 0; i < 18; ++i) {
                int idx = t + i * 256;       // 0..4607
                int col = idx & 63;
                int rk  = idx >> 6;          // 0..71
                Ws[idx] = src[rk * 1024 + col];
            }
        }
        __syncthreads();

#pragma unroll 1
        for (int cil = 0; cil < 8; ++cil) {
#pragma unroll
            for (int ky = 0; ky < 3; ++ky) {
                const float* xp = &Xs[cil * 120 + (r + ky) * 12 + ccB];
                float4 xa = *(const float4*)xp;
                float4 xb = *(const float4*)(xp + 4);
                float xv[8] = {xa.x, xa.y, xa.z, xa.w, xb.x, xb.y, xb.z, xb.w};
#pragma unroll
                for (int kx = 0; kx < 3; ++kx) {
                    float4 wv = *(const float4*)&Ws[(cil * 9 + ky * 3 + kx) * 64 + tx * 4];
                    float wr[4] = {wv.x, wv.y, wv.z, wv.w};
#pragma unroll
                    for (int i = 0; i < 4; ++i)
#pragma unroll
                        for (int j = 0; j < 4; ++j)
                            acc[i][j] += wr[i] * xv[kx + j];
                }
            }
        }
    }

    // Epilogue: co<256 -> xo half of d_out; co>=256 -> qkv scratch
#pragma unroll
    for (int i = 0; i < 4; ++i) {
        int co = coBase + tx * 4 + i;
#pragma unroll
        for (int j = 0; j < 4; ++j) {
            int p = (py0 + r) * 32 + px0 + ccB + j;
            float v = acc[i][j];
            if (co < 256) {
                out[(b * 512 + co) * 1024 + p] = v + bconv[co];
            } else {
                g_qkv[(b * 768 + co - 256) * 1024 + p] = v + bqkv[co - 256];
            }
        }
    }
}

// ---------------------------------------------------------------------------
// Kernel 2: flash attention per (b, h). One warp per query row (8 rows/block).
// Key/value tiles of 128 staged in smem; lane owns 4 keys; O partials in regs.
// Output written in the reference's reshape layout: channel = h*32 + m/32,
// y = m%32, x = d.
// ---------------------------------------------------------------------------
__global__ __launch_bounds__(256) void attention_kernel(
    const float* __restrict__ krw,   // key_rel_w (63, 32)
    const float* __restrict__ krh) { // key_rel_h (63, 32)
    __shared__ float kt[32 * 128];
    __shared__ float vt[32 * 128];
    __shared__ float relw[8][64];
    __shared__ float relh[8][64];

    const int t = threadIdx.x;
    const int lane = t & 31;
    const int w = t >> 5;
    const int b = blockIdx.z;
    const int h = blockIdx.y;
    const int m = blockIdx.x * 8 + w;   // query index in [0, 1024)
    const int qx = m >> 5;              // H index
    const int qy = m & 31;              // W index

    // Load scaled q row into registers (broadcast across lanes)
    const float* qbase = &g_qkv[(b * 768 + h * 32) * 1024 + m];
    float q[32];
#pragma unroll
    for (int d = 0; d < 32; ++d) q[d] = qbase[d * 1024] * 0.17677669529663687f;

    // Precompute rel dot products: rwq[mm] = q . key_rel_w[mm], similarly rhq
    for (int mm = lane; mm < 63; mm += 32) {
        float sw = 0.f, sh = 0.f;
#pragma unroll
        for (int d = 0; d < 32; ++d) {
            sw += q[d] * krw[mm * 32 + d];
            sh += q[d] * krh[mm * 32 + d];
        }
        relw[w][mm] = sw;
        relh[w][mm] = sh;
    }
    __syncwarp();

    float o[32];
#pragma unroll
    for (int d = 0; d < 32; ++d) o[d] = 0.f;
    float M = -1e30f, L = 0.f;

    const float* kg = &g_qkv[(b * 768 + 256 + h * 32) * 1024];
    const float* vg = &g_qkv[(b * 768 + 512 + h * 32) * 1024];

    for (int tile = 0; tile < 8; ++tile) {
        __syncthreads();
#pragma unroll
        for (int i = 0; i < 16; ++i) {
            int idx = t + i * 256;           // 0..4095
            int d  = idx >> 7;
            int nl = idx & 127;
            kt[idx] = kg[d * 1024 + tile * 128 + nl];
            vt[idx] = vg[d * 1024 + tile * 128 + nl];
        }
        __syncthreads();

        // S phase: 4 keys per lane
        float s0 = 0.f, s1 = 0.f, s2 = 0.f, s3 = 0.f;
#pragma unroll
        for (int d = 0; d < 32; ++d) {
            float4 kv = *(const float4*)&kt[d * 128 + lane * 4];
            s0 += q[d] * kv.x; s1 += q[d] * kv.y;
            s2 += q[d] * kv.z; s3 += q[d] * kv.w;
        }
        // relative position terms: key n = tile*128 + lane*4 + j
        {
            int n0 = tile * 128 + lane * 4;
            int i0 = n0 >> 5;         // key row (all 4 keys share it: lane*4+3 < next multiple of 32)
            int j0 = n0 & 31;         // key col base
            float rh = relh[w][i0 - qx + 31];
            s0 += relw[w][j0     - qy + 31] + rh;
            s1 += relw[w][j0 + 1 - qy + 31] + rh;
            s2 += relw[w][j0 + 2 - qy + 31] + rh;
            s3 += relw[w][j0 + 3 - qy + 31] + rh;
        }
        // Online softmax update
        float mx = fmaxf(fmaxf(s0, s1), fmaxf(s2, s3));
#pragma unroll
        for (int off = 16; off; off >>= 1)
            mx = fmaxf(mx, __shfl_xor_sync(0xffffffffu, mx, off));
        float newM = fmaxf(M, mx);
        float scale = __expf(M - newM);
        M = newM;
        float e0 = __expf(s0 - newM), e1 = __expf(s1 - newM);
        float e2 = __expf(s2 - newM), e3 = __expf(s3 - newM);
        L = L * scale + (e0 + e1) + (e2 + e3);
        // O phase
#pragma unroll
        for (int d = 0; d < 32; ++d) {
            float4 vv = *(const float4*)&vt[d * 128 + lane * 4];
            o[d] = o[d] * scale + e0 * vv.x + e1 * vv.y + e2 * vv.z + e3 * vv.w;
        }
    }

    // Cross-lane reductions
#pragma unroll
    for (int off = 16; off; off >>= 1)
        L += __shfl_xor_sync(0xffffffffu, L, off);
    float of = 0.f;
#pragma unroll
    for (int d = 0; d < 32; ++d) {
        float v = o[d];
#pragma unroll
        for (int off = 16; off; off >>= 1)
            v += __shfl_xor_sync(0xffffffffu, v, off);
        if (lane == d) of = v;
    }
    // att.reshape(b, DV, H, W): channel = h*32 + qx, y = qy, x = d(=lane)
    g_att[((b * 256 + h * 32 + qx) * 32 + qy) * 32 + lane] = of / L;
}

// ---------------------------------------------------------------------------
// Kernel 3: 1x1 conv (GEMM M=256, N=1024, K=256 per batch) -> out[:, 256:512]
// ---------------------------------------------------------------------------
__global__ __launch_bounds__(256) void conv1x1_kernel(
    const float* __restrict__ batt,
    float* __restrict__ out) {
    __shared__ float Wk[16 * 64];
    __shared__ float Ak[16 * 64];
    const int t  = threadIdx.x;
    const int tx = t & 15;
    const int ty = t >> 4;
    const int b      = blockIdx.z;
    const int coBase = blockIdx.x * 64;
    const int pBase  = blockIdx.y * 64;

    float acc[4][4];
#pragma unroll
    for (int i = 0; i < 4; ++i)
#pragma unroll
        for (int j = 0; j < 4; ++j) acc[i][j] = 0.f;

    for (int ciB = 0; ciB < 256; ciB += 16) {
        __syncthreads();
#pragma unroll
        for (int i = 0; i < 4; ++i) {
            int idx = t + i * 256;
            int col = idx & 63;
            int cil = idx >> 6;
            Wk[idx] = g_watT[(ciB + cil) * 256 + coBase + col];
            Ak[idx] = g_att[(b * 256 + ciB + cil) * 1024 + pBase + col];
        }
        __syncthreads();
#pragma unroll
        for (int cil = 0; cil < 16; ++cil) {
            float4 wv = *(const float4*)&Wk[cil * 64 + tx * 4];
            float4 av = *(const float4*)&Ak[cil * 64 + ty * 4];
            float wr[4] = {wv.x, wv.y, wv.z, wv.w};
            float ar[4] = {av.x, av.y, av.z, av.w};
#pragma unroll
            for (int i = 0; i < 4; ++i)
#pragma unroll
                for (int j = 0; j < 4; ++j)
                    acc[i][j] += wr[i] * ar[j];
        }
    }

#pragma unroll
    for (int i = 0; i < 4; ++i) {
        int co = coBase + tx * 4 + i;
        float bb = batt[co];
#pragma unroll
        for (int j = 0; j < 4; ++j) {
            int p = pBase + ty * 4 + j;
            out[(b * 512 + 256 + co) * 1024 + p] = acc[i][j] + bb;
        }
    }
}

// ---------------------------------------------------------------------------
// Launch
// ---------------------------------------------------------------------------
extern "C" void kernel_launch(void* const* d_in, const int* in_sizes, int n_in,
                              void* d_out, int out_size) {
    const float* x      = (const float*)d_in[0];
    const float* w_conv = (const float*)d_in[1];
    const float* b_conv = (const float*)d_in[2];
    const float* w_qkv  = (const float*)d_in[3];
    const float* b_qkv  = (const float*)d_in[4];
    const float* w_att  = (const float*)d_in[5];
    const float* b_att  = (const float*)d_in[6];
    const float* krw    = (const float*)d_in[7];
    const float* krh    = (const float*)d_in[8];
    float* out = (float*)d_out;

    prep_weights<<<(2304 * 1024 + 255) / 256, 256>>>(w_conv, w_qkv, w_att);
    conv3x3_kernel<<<dim3(16, 16, 8), 256>>>(x, b_conv, b_qkv, out);
    attention_kernel<<<dim3(128, 8, 8), 256>>>(krw, krh);
    conv1x1_kernel<<<dim3(4, 16, 8), 256>>>(b_att, out);
}

// round 4
// speedup vs baseline: 1.6019x; 1.6019x over previous
#include <cuda_runtime.h>
#include <cuda_bf16.h>

// Problem constants
// B=8, CIN=256, COUT=512, DK=256, DV=256, NH=8, H=W=32, DKH=DVH=32
#define HW 1024

// Scratch (static device globals: allocation-free rule)
__device__ float g_wT[2304 * 1024];      // combined conv weights, K-major: [(ci*9+k)][co] co: 0..255 conv, 256..1023 qkv
__device__ float g_watT[256 * 256];      // w_att transposed: [ci][co]
__device__ float g_qkv[8 * 768 * 1024];  // qkv conv output (b, 768, HW)
__device__ float g_att[8 * 256 * 1024];  // attention output, already in (b, C, H, W) layout for 1x1 conv

// ---------------------------------------------------------------------------
// Kernel 0: weight preparation (transpose to K-major)
// ---------------------------------------------------------------------------
__global__ void prep_weights(const float* __restrict__ wc,
                             const float* __restrict__ wq,
                             const float* __restrict__ wa) {
    int idx = blockIdx.x * 256 + threadIdx.x;
    if (idx < 2304 * 1024) {
        int co = idx & 1023;
        int rk = idx >> 10;          // ci*9 + k
        int ci = rk / 9;
        int k  = rk - ci * 9;
        float v = (co < 256) ? wc[(co * 256 + ci) * 9 + k]
                             : wq[((co - 256) * 256 + ci) * 9 + k];
        g_wT[idx] = v;
    }
    if (idx < 256 * 256) {
        int co = idx & 255;
        int ci = idx >> 8;
        g_watT[idx] = wa[co * 256 + ci];
    }
}

// ---------------------------------------------------------------------------
// Kernel 1: fused 3x3 conv (1024 output channels = 256 xo + 768 qkv)
// Block: 256 threads, tile = 64 co x 64 pixels (8x8 spatial), 4x4 per thread.
// ---------------------------------------------------------------------------
__global__ __launch_bounds__(256) void conv3x3_kernel(
    const float* __restrict__ x,
    const float* __restrict__ bconv,
    const float* __restrict__ bqkv,
    float* __restrict__ out) {
    __shared__ float Ws[72 * 64];      // [cil*9+k][64 co]
    __shared__ float Xs[8 * 10 * 12];  // [cil][10 rows][12 pitch]

    const int t  = threadIdx.x;
    const int tx = t & 15;       // co group
    const int ty = t >> 4;       // pixel group
    const int b      = blockIdx.z;
    const int coBase = blockIdx.x * 64;
    const int pt     = blockIdx.y;
    const int py0 = (pt >> 2) * 8;
    const int px0 = (pt & 3) * 8;
    const int r   = ty >> 1;           // row within 8x8 tile
    const int ccB = (ty & 1) * 4;      // col base within 8x8 tile

    float acc[4][4];
#pragma unroll
    for (int i = 0; i < 4; ++i)
#pragma unroll
        for (int j = 0; j < 4; ++j) acc[i][j] = 0.f;

    for (int ciBase = 0; ciBase < 256; ciBase += 8) {
        __syncthreads();
        // Load input patch with halo (8 ci x 10 x 10), zero-padded
#pragma unroll
        for (int i = 0; i < 4; ++i) {
            int idx = t + i * 256;
            if (idx < 800) {
                int cil = idx / 100;
                int rem = idx - cil * 100;
                int ly = rem / 10;
                int lx = rem - ly * 10;
                int gy = py0 + ly - 1;
                int gx = px0 + lx - 1;
                float v = 0.f;
                if ((unsigned)gy < 32u && (unsigned)gx < 32u)
                    v = x[((b * 256 + ciBase + cil) * 32 + gy) * 32 + gx];
                Xs[cil * 120 + ly * 12 + lx] = v;
            }
        }
        // Load weights (coalesced from K-major transposed buffer)
        {
            const float* src = &g_wT[(ciBase * 9) * 1024 + coBase];
#pragma unroll
            for (int i = 0; i < 18; ++i) {
                int idx = t + i * 256;       // 0..4607
                int col = idx & 63;
                int rk  = idx >> 6;          // 0..71
                Ws[idx] = src[rk * 1024 + col];
            }
        }
        __syncthreads();

#pragma unroll 1
        for (int cil = 0; cil < 8; ++cil) {
#pragma unroll
            for (int ky = 0; ky < 3; ++ky) {
                const float* xp = &Xs[cil * 120 + (r + ky) * 12 + ccB];
                float4 xa = *(const float4*)xp;
                float4 xb = *(const float4*)(xp + 4);
                float xv[8] = {xa.x, xa.y, xa.z, xa.w, xb.x, xb.y, xb.z, xb.w};
#pragma unroll
                for (int kx = 0; kx < 3; ++kx) {
                    float4 wv = *(const float4*)&Ws[(cil * 9 + ky * 3 + kx) * 64 + tx * 4];
                    float wr[4] = {wv.x, wv.y, wv.z, wv.w};
#pragma unroll
                    for (int i = 0; i < 4; ++i)
#pragma unroll
                        for (int j = 0; j < 4; ++j)
                            acc[i][j] += wr[i] * xv[kx + j];
                }
            }
        }
    }

    // Epilogue: co<256 -> xo half of d_out; co>=256 -> qkv scratch
#pragma unroll
    for (int i = 0; i < 4; ++i) {
        int co = coBase + tx * 4 + i;
#pragma unroll
        for (int j = 0; j < 4; ++j) {
            int p = (py0 + r) * 32 + px0 + ccB + j;
            float v = acc[i][j];
            if (co < 256) {
                out[(b * 512 + co) * 1024 + p] = v + bconv[co];
            } else {
                g_qkv[(b * 768 + co - 256) * 1024 + p] = v + bqkv[co - 256];
            }
        }
    }
}

// ---------------------------------------------------------------------------
// Kernel 2: flash attention per (b, h). One warp per query row (8 rows/block).
// Key/value tiles of 128 staged in smem; lane owns 4 keys; O partials in regs.
// Output written in the reference's reshape layout: channel = h*32 + m/32,
// y = m%32, x = d.
// ---------------------------------------------------------------------------
__global__ __launch_bounds__(256) void attention_kernel(
    const float* __restrict__ krw,   // key_rel_w (63, 32)
    const float* __restrict__ krh) { // key_rel_h (63, 32)
    __shared__ float kt[32 * 128];
    __shared__ float vt[32 * 128];
    __shared__ float relw[8][64];
    __shared__ float relh[8][64];

    const int t = threadIdx.x;
    const int lane = t & 31;
    const int w = t >> 5;
    const int b = blockIdx.z;
    const int h = blockIdx.y;
    const int m = blockIdx.x * 8 + w;   // query index in [0, 1024)
    const int qx = m >> 5;              // H index
    const int qy = m & 31;              // W index

    // Load scaled q row into registers (broadcast across lanes)
    const float* qbase = &g_qkv[(b * 768 + h * 32) * 1024 + m];
    float q[32];
#pragma unroll
    for (int d = 0; d < 32; ++d) q[d] = qbase[d * 1024] * 0.17677669529663687f;

    // Precompute rel dot products: rwq[mm] = q . key_rel_w[mm], similarly rhq
    for (int mm = lane; mm < 63; mm += 32) {
        float sw = 0.f, sh = 0.f;
#pragma unroll
        for (int d = 0; d < 32; ++d) {
            sw += q[d] * krw[mm * 32 + d];
            sh += q[d] * krh[mm * 32 + d];
        }
        relw[w][mm] = sw;
        relh[w][mm] = sh;
    }
    __syncwarp();

    float o[32];
#pragma unroll
    for (int d = 0; d < 32; ++d) o[d] = 0.f;
    float M = -1e30f, L = 0.f;

    const float* kg = &g_qkv[(b * 768 + 256 + h * 32) * 1024];
    const float* vg = &g_qkv[(b * 768 + 512 + h * 32) * 1024];

    for (int tile = 0; tile < 8; ++tile) {
        __syncthreads();
#pragma unroll
        for (int i = 0; i < 16; ++i) {
            int idx = t + i * 256;           // 0..4095
            int d  = idx >> 7;
            int nl = idx & 127;
            kt[idx] = kg[d * 1024 + tile * 128 + nl];
            vt[idx] = vg[d * 1024 + tile * 128 + nl];
        }
        __syncthreads();

        // S phase: 4 keys per lane
        float s0 = 0.f, s1 = 0.f, s2 = 0.f, s3 = 0.f;
#pragma unroll
        for (int d = 0; d < 32; ++d) {
            float4 kv = *(const float4*)&kt[d * 128 + lane * 4];
            s0 += q[d] * kv.x; s1 += q[d] * kv.y;
            s2 += q[d] * kv.z; s3 += q[d] * kv.w;
        }
        // relative position terms: key n = tile*128 + lane*4 + j
        {
            int n0 = tile * 128 + lane * 4;
            int i0 = n0 >> 5;         // key row (all 4 keys share it: lane*4+3 < next multiple of 32)
            int j0 = n0 & 31;         // key col base
            float rh = relh[w][i0 - qx + 31];
            s0 += relw[w][j0     - qy + 31] + rh;
            s1 += relw[w][j0 + 1 - qy + 31] + rh;
            s2 += relw[w][j0 + 2 - qy + 31] + rh;
            s3 += relw[w][j0 + 3 - qy + 31] + rh;
        }
        // Online softmax update
        float mx = fmaxf(fmaxf(s0, s1), fmaxf(s2, s3));
#pragma unroll
        for (int off = 16; off; off >>= 1)
            mx = fmaxf(mx, __shfl_xor_sync(0xffffffffu, mx, off));
        float newM = fmaxf(M, mx);
        float scale = __expf(M - newM);
        M = newM;
        float e0 = __expf(s0 - newM), e1 = __expf(s1 - newM);
        float e2 = __expf(s2 - newM), e3 = __expf(s3 - newM);
        L = L * scale + (e0 + e1) + (e2 + e3);
        // O phase
#pragma unroll
        for (int d = 0; d < 32; ++d) {
            float4 vv = *(const float4*)&vt[d * 128 + lane * 4];
            o[d] = o[d] * scale + e0 * vv.x + e1 * vv.y + e2 * vv.z + e3 * vv.w;
        }
    }

    // Cross-lane reductions
#pragma unroll
    for (int off = 16; off; off >>= 1)
        L += __shfl_xor_sync(0xffffffffu, L, off);
    float of = 0.f;
#pragma unroll
    for (int d = 0; d < 32; ++d) {
        float v = o[d];
#pragma unroll
        for (int off = 16; off; off >>= 1)
            v += __shfl_xor_sync(0xffffffffu, v, off);
        if (lane == d) of = v;
    }
    // att.reshape(b, DV, H, W): channel = h*32 + qx, y = qy, x = d(=lane)
    g_att[((b * 256 + h * 32 + qx) * 32 + qy) * 32 + lane] = of / L;
}

// ---------------------------------------------------------------------------
// Kernel 3: 1x1 conv (GEMM M=256, N=1024, K=256 per batch) -> out[:, 256:512]
// ---------------------------------------------------------------------------
__global__ __launch_bounds__(256) void conv1x1_kernel(
    const float* __restrict__ batt,
    float* __restrict__ out) {
    __shared__ float Wk[16 * 64];
    __shared__ float Ak[16 * 64];
    const int t  = threadIdx.x;
    const int tx = t & 15;
    const int ty = t >> 4;
    const int b      = blockIdx.z;
    const int coBase = blockIdx.x * 64;
    const int pBase  = blockIdx.y * 64;

    float acc[4][4];
#pragma unroll
    for (int i = 0; i < 4; ++i)
#pragma unroll
        for (int j = 0; j < 4; ++j) acc[i][j] = 0.f;

    for (int ciB = 0; ciB < 256; ciB += 16) {
        __syncthreads();
#pragma unroll
        for (int i = 0; i < 4; ++i) {
            int idx = t + i * 256;
            int col = idx & 63;
            int cil = idx >> 6;
            Wk[idx] = g_watT[(ciB + cil) * 256 + coBase + col];
            Ak[idx] = g_att[(b * 256 + ciB + cil) * 1024 + pBase + col];
        }
        __syncthreads();
#pragma unroll
        for (int cil = 0; cil < 16; ++cil) {
            float4 wv = *(const float4*)&Wk[cil * 64 + tx * 4];
            float4 av = *(const float4*)&Ak[cil * 64 + ty * 4];
            float wr[4] = {wv.x, wv.y, wv.z, wv.w};
            float ar[4] = {av.x, av.y, av.z, av.w};
#pragma unroll
            for (int i = 0; i < 4; ++i)
#pragma unroll
                for (int j = 0; j < 4; ++j)
                    acc[i][j] += wr[i] * ar[j];
        }
    }

#pragma unroll
    for (int i = 0; i < 4; ++i) {
        int co = coBase + tx * 4 + i;
        float bb = batt[co];
#pragma unroll
        for (int j = 0; j < 4; ++j) {
            int p = pBase + ty * 4 + j;
            out[(b * 512 + 256 + co) * 1024 + p] = acc[i][j] + bb;
        }
    }
}

// ---------------------------------------------------------------------------
// Launch
// ---------------------------------------------------------------------------
extern "C" void kernel_launch(void* const* d_in, const int* in_sizes, int n_in,
                              void* d_out, int out_size) {
    const float* x      = (const float*)d_in[0];
    const float* w_conv = (const float*)d_in[1];
    const float* b_conv = (const float*)d_in[2];
    const float* w_qkv  = (const float*)d_in[3];
    const float* b_qkv  = (const float*)d_in[4];
    const float* w_att  = (const float*)d_in[5];
    const float* b_att  = (const float*)d_in[6];
    const float* krw    = (const float*)d_in[7];
    const float* krh    = (const float*)d_in[8];
    float* out = (float*)d_out;

    prep_weights<<<(2304 * 1024 + 255) / 256, 256>>>(w_conv, w_qkv, w_att);
    conv3x3_kernel<<<dim3(16, 16, 8), 256>>>(x, b_conv, b_qkv, out);
    attention_kernel<<<dim3(128, 8, 8), 256>>>(krw, krh);
    conv1x1_kernel<<<dim3(4, 16, 8), 256>>>(b_att, out);
}

// round 6
// speedup vs baseline: 1.9423x; 1.2125x over previous
#include <cuda_runtime.h>
#include <cuda_bf16.h>
#include <cstdint>

// Problem: B=8, CIN=256, COUT=512, DK=DV=256, NH=8, H=W=32
// conv3x3 as split-bf16 mma.sync GEMM: D[8192 px, 1024 co], K=2304

// Scratch (static device globals: allocation-free rule)
__device__ __nv_bfloat16 g_colh[8192 * 2304];  // im2col hi plane [n][k]
__device__ __nv_bfloat16 g_coll[8192 * 2304];  // im2col lo plane
__device__ __nv_bfloat16 g_wh[1024 * 2304];    // weights hi [co][k] (conv||qkv)
__device__ __nv_bfloat16 g_wl[1024 * 2304];    // weights lo
__device__ float g_watT[256 * 256];            // w_att transposed [ci][co]
__device__ float g_qkv[8 * 768 * 1024];        // qkv conv output (b, 768, HW)
__device__ float g_att[8 * 256 * 1024];        // attention out, (b, C, H, W)

// ---------------------------------------------------------------------------
// Helpers (sm_80-era ISA only: cp.async, ldmatrix, mma.sync — safe on sm_103)
// ---------------------------------------------------------------------------
__device__ __forceinline__ uint32_t smem_u32(const void* p) {
    uint32_t a;
    asm("{ .reg .u64 t; cvta.to.shared.u64 t, %1; cvt.u32.u64 %0, t; }"
        : "=r"(a) : "l"(p));
    return a;
}
#define SWZ128(o) ((o) ^ (((o) >> 3) & 0x70))

#define CP_ASYNC16(dst, src) \
    asm volatile("cp.async.cg.shared.global [%0], [%1], 16;" :: "r"(dst), "l"(src))
#define CP_COMMIT() asm volatile("cp.async.commit_group;" ::: "memory")
#define CP_WAIT(n)  asm volatile("cp.async.wait_group %0;" :: "n"(n) : "memory")

__device__ __forceinline__ void ldsm4(uint32_t* r, uint32_t a) {
    asm volatile("ldmatrix.sync.aligned.m8n8.x4.shared.b16 {%0,%1,%2,%3}, [%4];"
                 : "=r"(r[0]), "=r"(r[1]), "=r"(r[2]), "=r"(r[3]) : "r"(a));
}
__device__ __forceinline__ void mma16816(float* c, const uint32_t* a, const uint32_t* b) {
    asm volatile(
        "mma.sync.aligned.m16n8k16.row.col.f32.bf16.bf16.f32 "
        "{%0,%1,%2,%3}, {%4,%5,%6,%7}, {%8,%9}, {%0,%1,%2,%3};"
        : "+f"(c[0]), "+f"(c[1]), "+f"(c[2]), "+f"(c[3])
        : "r"(a[0]), "r"(a[1]), "r"(a[2]), "r"(a[3]), "r"(b[0]), "r"(b[1]));
}

// ---------------------------------------------------------------------------
// Prep kernels: split-bf16 im2col + weight planes + 1x1 weight transpose
// ---------------------------------------------------------------------------
__global__ void im2col_k(const float* __restrict__ x) {
    int k = blockIdx.x * 256 + threadIdx.x;   // 0..2303 (grid.x = 9)
    int n = blockIdx.y;                       // 0..8191
    int b = n >> 10, p = n & 1023, py = p >> 5, px = p & 31;
    int ci = k / 9, r = k - ci * 9;
    int ky = r / 3, kx = r - ky * 3;
    int gy = py + ky - 1, gx = px + kx - 1;
    float v = 0.f;
    if ((unsigned)gy < 32u && (unsigned)gx < 32u)
        v = x[((b * 256 + ci) * 32 + gy) * 32 + gx];
    __nv_bfloat16 hi = __float2bfloat16(v);
    float lo = v - __bfloat162float(hi);
    g_colh[(size_t)n * 2304 + k] = hi;
    g_coll[(size_t)n * 2304 + k] = __float2bfloat16(lo);
}

__global__ void prep_w(const float* __restrict__ wc, const float* __restrict__ wq) {
    int k = blockIdx.x * 256 + threadIdx.x;   // grid.x = 9
    int co = blockIdx.y;                      // 0..1023
    float v = (co < 256) ? wc[co * 2304 + k] : wq[(co - 256) * 2304 + k];
    __nv_bfloat16 hi = __float2bfloat16(v);
    float lo = v - __bfloat162float(hi);
    g_wh[(size_t)co * 2304 + k] = hi;
    g_wl[(size_t)co * 2304 + k] = __float2bfloat16(lo);
}

__global__ void prep_att(const float* __restrict__ wa) {
    int idx = blockIdx.x * 256 + threadIdx.x; // 65536
    int ci = idx >> 8, co = idx & 255;
    g_watT[ci * 256 + co] = wa[co * 256 + ci];
}

// ---------------------------------------------------------------------------
// split-bf16 mma.sync GEMM: CTA tile = 128 px (M) x 128 co (N), K=2304
// 8 warps (2 M-groups? no: 4 M x 2 N), warp tile 32x64.
// 2-stage cp.async pipeline, 64KB/stage (Ah|Al|Bh|Bl planes, SW128 rows).
// ---------------------------------------------------------------------------
__global__ __launch_bounds__(256) void conv_mma(
    const float* __restrict__ bconv,
    const float* __restrict__ bqkv,
    float* __restrict__ out) {
    extern __shared__ char dsm[];
    char* sb = (char*)(((uintptr_t)dsm + 1023) & ~(uintptr_t)1023);
    const uint32_t sbu = smem_u32(sb);

    const int t = threadIdx.x;
    const int lane = t & 31;
    const int wid = t >> 5;
    const int warpM = wid >> 1;          // 0..3 -> 32 px rows
    const int warpN = wid & 1;           // 0..1 -> 64 co cols
    const int nBase = blockIdx.x * 128;  // pixel tile
    const int coBase = blockIdx.y * 128; // channel tile

    // ldmatrix lane address components
    const int la = lane & 15;                 // A row within 16
    const int lb = (lane >> 4) << 4;          // A col half (bytes)
    const int bg = lane >> 3;                 // B group 0..3
    const int brow = ((bg >> 1) << 3) + (lane & 7);  // B row within 16
    const int bcolh = (bg & 1) << 4;          // B col half (bytes)

    float acc[64];
#pragma unroll
    for (int i = 0; i < 64; ++i) acc[i] = 0.f;

#define LOAD_PLANE(gbase, rowoff, dstoff, kbyte, buf) \
    _Pragma("unroll") \
    for (int i = 0; i < 4; ++i) { \
        int idx = t + i * 256; \
        int row = idx >> 3; \
        int jc  = idx & 7; \
        const char* src = (const char*)(gbase) + (size_t)((rowoff) + row) * 4608 + (kbyte) + jc * 16; \
        uint32_t dst = sbu + (buf) * 65536 + (dstoff) + SWZ128(row * 128 + jc * 16); \
        CP_ASYNC16(dst, src); \
    }

#define LOAD_STAGE(buf, kbyte) do { \
        LOAD_PLANE(g_colh, nBase, 0,     (kbyte), (buf)); \
        LOAD_PLANE(g_coll, nBase, 16384, (kbyte), (buf)); \
        LOAD_PLANE(g_wh,  coBase, 32768, (kbyte), (buf)); \
        LOAD_PLANE(g_wl,  coBase, 49152, (kbyte), (buf)); \
    } while (0)

    LOAD_STAGE(0, 0);
    CP_COMMIT();

#pragma unroll 1
    for (int s = 0; s < 36; ++s) {
        if (s < 35) {
            LOAD_STAGE((s + 1) & 1, (size_t)(s + 1) * 128);
            CP_COMMIT();
            CP_WAIT(1);
        } else {
            CP_WAIT(0);
        }
        __syncthreads();

        const uint32_t base = sbu + (s & 1) * 65536;
        const uint32_t pAh = base, pAl = base + 16384;
        const uint32_t pBh = base + 32768, pBl = base + 49152;

#pragma unroll
        for (int kk = 0; kk < 4; ++kk) {
            uint32_t ah[8], al[8], bh[16], bl[16];
            const int acol = kk * 32 + lb;
            const int bcol = kk * 32 + bcolh;
#pragma unroll
            for (int mt = 0; mt < 2; ++mt) {
                int row = warpM * 32 + mt * 16 + la;
                ldsm4(ah + 4 * mt, pAh + SWZ128(row * 128 + acol));
                ldsm4(al + 4 * mt, pAl + SWZ128(row * 128 + acol));
            }
#pragma unroll
            for (int ntb = 0; ntb < 4; ++ntb) {
                int row = warpN * 64 + ntb * 16 + brow;
                ldsm4(bh + 4 * ntb, pBh + SWZ128(row * 128 + bcol));
                ldsm4(bl + 4 * ntb, pBl + SWZ128(row * 128 + bcol));
            }
#pragma unroll
            for (int mt = 0; mt < 2; ++mt)
#pragma unroll
                for (int nt = 0; nt < 8; ++nt) {
                    float* c = acc + (mt * 8 + nt) * 4;
                    mma16816(c, ah + 4 * mt, bh + 2 * nt);  // Ah*Bh
                    mma16816(c, ah + 4 * mt, bl + 2 * nt);  // Ah*Bl
                    mma16816(c, al + 4 * mt, bh + 2 * nt);  // Al*Bh
                }
        }
        __syncthreads();
    }

    // Epilogue: transpose through smem -> coalesced global stores (+bias)
    float* sf = (float*)sb;   // 128 co x 132 px (padded)
#pragma unroll
    for (int mt = 0; mt < 2; ++mt)
#pragma unroll
        for (int nt = 0; nt < 8; ++nt) {
            const float* c = acc + (mt * 8 + nt) * 4;
            int px0 = warpM * 32 + mt * 16 + (lane >> 2);
            int co0 = warpN * 64 + nt * 8 + (lane & 3) * 2;
            sf[co0 * 132 + px0]           = c[0];
            sf[(co0 + 1) * 132 + px0]     = c[1];
            sf[co0 * 132 + px0 + 8]       = c[2];
            sf[(co0 + 1) * 132 + px0 + 8] = c[3];
        }
    __syncthreads();

    const int b = nBase >> 10;
    const int p0 = nBase & 1023;
#pragma unroll 4
    for (int i = 0; i < 64; ++i) {
        int idx = t + i * 256;
        int co_l = idx >> 7;
        int px_l = idx & 127;
        float v = sf[co_l * 132 + px_l];
        int co = coBase + co_l;
        int p = p0 + px_l;
        if (coBase < 256) {
            out[((size_t)b * 512 + co) * 1024 + p] = v + __ldg(&bconv[co]);
        } else {
            g_qkv[((size_t)b * 768 + co - 256) * 1024 + p] = v + __ldg(&bqkv[co - 256]);
        }
    }
}

// ---------------------------------------------------------------------------
// Kernel 2: flash attention per (b, h). One warp per query row (unchanged).
// ---------------------------------------------------------------------------
__global__ __launch_bounds__(256) void attention_kernel(
    const float* __restrict__ krw,
    const float* __restrict__ krh) {
    __shared__ float kt[32 * 128];
    __shared__ float vt[32 * 128];
    __shared__ float relw[8][64];
    __shared__ float relh[8][64];

    const int t = threadIdx.x;
    const int lane = t & 31;
    const int w = t >> 5;
    const int b = blockIdx.z;
    const int h = blockIdx.y;
    const int m = blockIdx.x * 8 + w;
    const int qx = m >> 5;
    const int qy = m & 31;

    const float* qbase = &g_qkv[(b * 768 + h * 32) * 1024 + m];
    float q[32];
#pragma unroll
    for (int d = 0; d < 32; ++d) q[d] = qbase[d * 1024] * 0.17677669529663687f;

    for (int mm = lane; mm < 63; mm += 32) {
        float sw = 0.f, sh = 0.f;
#pragma unroll
        for (int d = 0; d < 32; ++d) {
            sw += q[d] * krw[mm * 32 + d];
            sh += q[d] * krh[mm * 32 + d];
        }
        relw[w][mm] = sw;
        relh[w][mm] = sh;
    }
    __syncwarp();

    float o[32];
#pragma unroll
    for (int d = 0; d < 32; ++d) o[d] = 0.f;
    float M = -1e30f, L = 0.f;

    const float* kg = &g_qkv[(b * 768 + 256 + h * 32) * 1024];
    const float* vg = &g_qkv[(b * 768 + 512 + h * 32) * 1024];

    for (int tile = 0; tile < 8; ++tile) {
        __syncthreads();
#pragma unroll
        for (int i = 0; i < 16; ++i) {
            int idx = t + i * 256;
            int d = idx >> 7;
            int nl = idx & 127;
            kt[idx] = kg[d * 1024 + tile * 128 + nl];
            vt[idx] = vg[d * 1024 + tile * 128 + nl];
        }
        __syncthreads();

        float s0 = 0.f, s1 = 0.f, s2 = 0.f, s3 = 0.f;
#pragma unroll
        for (int d = 0; d < 32; ++d) {
            float4 kv = *(const float4*)&kt[d * 128 + lane * 4];
            s0 += q[d] * kv.x; s1 += q[d] * kv.y;
            s2 += q[d] * kv.z; s3 += q[d] * kv.w;
        }
        {
            int n0 = tile * 128 + lane * 4;
            int i0 = n0 >> 5;
            int j0 = n0 & 31;
            float rh = relh[w][i0 - qx + 31];
            s0 += relw[w][j0     - qy + 31] + rh;
            s1 += relw[w][j0 + 1 - qy + 31] + rh;
            s2 += relw[w][j0 + 2 - qy + 31] + rh;
            s3 += relw[w][j0 + 3 - qy + 31] + rh;
        }
        float mx = fmaxf(fmaxf(s0, s1), fmaxf(s2, s3));
#pragma unroll
        for (int off = 16; off; off >>= 1)
            mx = fmaxf(mx, __shfl_xor_sync(0xffffffffu, mx, off));
        float newM = fmaxf(M, mx);
        float scale = __expf(M - newM);
        M = newM;
        float e0 = __expf(s0 - newM), e1 = __expf(s1 - newM);
        float e2 = __expf(s2 - newM), e3 = __expf(s3 - newM);
        L = L * scale + (e0 + e1) + (e2 + e3);
#pragma unroll
        for (int d = 0; d < 32; ++d) {
            float4 vv = *(const float4*)&vt[d * 128 + lane * 4];
            o[d] = o[d] * scale + e0 * vv.x + e1 * vv.y + e2 * vv.z + e3 * vv.w;
        }
    }

#pragma unroll
    for (int off = 16; off; off >>= 1)
        L += __shfl_xor_sync(0xffffffffu, L, off);
    float of = 0.f;
#pragma unroll
    for (int d = 0; d < 32; ++d) {
        float v = o[d];
#pragma unroll
        for (int off = 16; off; off >>= 1)
            v += __shfl_xor_sync(0xffffffffu, v, off);
        if (lane == d) of = v;
    }
    g_att[((b * 256 + h * 32 + qx) * 32 + qy) * 32 + lane] = of / L;
}

// ---------------------------------------------------------------------------
// Kernel 3: 1x1 conv (unchanged)
// ---------------------------------------------------------------------------
__global__ __launch_bounds__(256) void conv1x1_kernel(
    const float* __restrict__ batt,
    float* __restrict__ out) {
    __shared__ float Wk[16 * 64];
    __shared__ float Ak[16 * 64];
    const int t = threadIdx.x;
    const int tx = t & 15;
    const int ty = t >> 4;
    const int b = blockIdx.z;
    const int coBase = blockIdx.x * 64;
    const int pBase = blockIdx.y * 64;

    float acc[4][4];
#pragma unroll
    for (int i = 0; i < 4; ++i)
#pragma unroll
        for (int j = 0; j < 4; ++j) acc[i][j] = 0.f;

    for (int ciB = 0; ciB < 256; ciB += 16) {
        __syncthreads();
#pragma unroll
        for (int i = 0; i < 4; ++i) {
            int idx = t + i * 256;
            int col = idx & 63;
            int cil = idx >> 6;
            Wk[idx] = g_watT[(ciB + cil) * 256 + coBase + col];
            Ak[idx] = g_att[(b * 256 + ciB + cil) * 1024 + pBase + col];
        }
        __syncthreads();
#pragma unroll
        for (int cil = 0; cil < 16; ++cil) {
            float4 wv = *(const float4*)&Wk[cil * 64 + tx * 4];
            float4 av = *(const float4*)&Ak[cil * 64 + ty * 4];
            float wr[4] = {wv.x, wv.y, wv.z, wv.w};
            float ar[4] = {av.x, av.y, av.z, av.w};
#pragma unroll
            for (int i = 0; i < 4; ++i)
#pragma unroll
                for (int j = 0; j < 4; ++j)
                    acc[i][j] += wr[i] * ar[j];
        }
    }

#pragma unroll
    for (int i = 0; i < 4; ++i) {
        int co = coBase + tx * 4 + i;
        float bb = batt[co];
#pragma unroll
        for (int j = 0; j < 4; ++j) {
            int p = pBase + ty * 4 + j;
            out[(b * 512 + 256 + co) * 1024 + p] = acc[i][j] + bb;
        }
    }
}

// ---------------------------------------------------------------------------
// Launch
// ---------------------------------------------------------------------------
extern "C" void kernel_launch(void* const* d_in, const int* in_sizes, int n_in,
                              void* d_out, int out_size) {
    const float* x      = (const float*)d_in[0];
    const float* w_conv = (const float*)d_in[1];
    const float* b_conv = (const float*)d_in[2];
    const float* w_qkv  = (const float*)d_in[3];
    const float* b_qkv  = (const float*)d_in[4];
    const float* w_att  = (const float*)d_in[5];
    const float* b_att  = (const float*)d_in[6];
    const float* krw    = (const float*)d_in[7];
    const float* krh    = (const float*)d_in[8];
    float* out = (float*)d_out;

    static int smem_set = 0;
    if (!smem_set) {
        cudaFuncSetAttribute(conv_mma, cudaFuncAttributeMaxDynamicSharedMemorySize, 132096);
        smem_set = 1;
    }

    im2col_k<<<dim3(9, 8192), 256>>>(x);
    prep_w<<<dim3(9, 1024), 256>>>(w_conv, w_qkv);
    prep_att<<<256, 256>>>(w_att);
    conv_mma<<<dim3(64, 8), 256, 132096>>>(b_conv, b_qkv, out);
    attention_kernel<<<dim3(128, 8, 8), 256>>>(krw, krh);
    conv1x1_kernel<<<dim3(4, 16, 8), 256>>>(b_att, out);
}